// round 13
// baseline (speedup 1.0000x reference)
#include <cuda_runtime.h>
#include <cuda_fp16.h>

#define NN 50000
#define NP 52096          // padded rows (296*176)
#define EE 800000
#define DD 128
#define EPS 1e-5f
#define SQRTD 11.313708498984761f

typedef unsigned int u32;

__device__ __align__(16) float g_x[(long long)NP * DD];
__device__ __align__(16) __half g_x16[(long long)NP * DD];   // fp16 mirror of x
__device__ __align__(16) __half g_a16[(long long)NP * DD];   // fp16 aggregation
// weights, transposed [layer][n][k]: Wl as fp16 hi/lo pair (exact-ish), Wr fp16
__device__ __align__(16) __half g_Wlh[3 * DD * DD];
__device__ __align__(16) __half g_Wll[3 * DD * DD];
__device__ __align__(16) __half g_Wr16[3 * DD * DD];
// CSR (by dst)
__device__ int g_cnt[NN];
__device__ int g_rowptr[NN + 1];
__device__ __align__(16) int g_eoff[EE];
__device__ int g_esrc[EE];

__device__ __forceinline__ float4 ld4(const float* __restrict__ p) {
    return *reinterpret_cast<const float4*>(p);
}

__device__ __forceinline__ u32 pack_h2(float a, float b) {
    __half2 h = __floats2half2_rn(a, b);
    return *reinterpret_cast<u32*>(&h);
}

__device__ __forceinline__ void mma16816h(float* d, const u32* a, const u32* b) {
    asm volatile(
        "mma.sync.aligned.m16n8k16.row.col.f32.f16.f16.f32 "
        "{%0,%1,%2,%3}, {%4,%5,%6,%7}, {%8,%9}, {%0,%1,%2,%3};"
        : "+f"(d[0]), "+f"(d[1]), "+f"(d[2]), "+f"(d[3])
        : "r"(a[0]), "r"(a[1]), "r"(a[2]), "r"(a[3]), "r"(b[0]), "r"(b[1]));
}

// ---------------- CSR build ----------------
__global__ void __launch_bounds__(256) zero_cnt_kernel()
{
    int i = blockIdx.x * 256 + threadIdx.x;
    if (i < NN) g_cnt[i] = 0;
}

__global__ void __launch_bounds__(256) hist_off_kernel(const int* __restrict__ edge)
{
    int i = blockIdx.x * 256 + threadIdx.x;
    if (i >= EE / 8) return;
    int4 d0 = __ldg(reinterpret_cast<const int4*>(edge + EE) + 2 * i);
    int4 d1 = __ldg(reinterpret_cast<const int4*>(edge + EE) + 2 * i + 1);
    int4 o0, o1;
    o0.x = atomicAdd(&g_cnt[d0.x], 1);
    o0.y = atomicAdd(&g_cnt[d0.y], 1);
    o0.z = atomicAdd(&g_cnt[d0.z], 1);
    o0.w = atomicAdd(&g_cnt[d0.w], 1);
    o1.x = atomicAdd(&g_cnt[d1.x], 1);
    o1.y = atomicAdd(&g_cnt[d1.y], 1);
    o1.z = atomicAdd(&g_cnt[d1.z], 1);
    o1.w = atomicAdd(&g_cnt[d1.w], 1);
    reinterpret_cast<int4*>(g_eoff)[2 * i]     = o0;
    reinterpret_cast<int4*>(g_eoff)[2 * i + 1] = o1;
}

__global__ void __launch_bounds__(1024) scan_kernel()
{
    __shared__ int part[1024];
    int t = threadIdx.x;
    int base = t * 49;
    int s = 0;
    for (int i = 0; i < 49; i++) {
        int idx = base + i;
        if (idx < NN) s += g_cnt[idx];
    }
    part[t] = s;
    __syncthreads();
    for (int off = 1; off < 1024; off <<= 1) {
        int add = (t >= off) ? part[t - off] : 0;
        __syncthreads();
        part[t] += add;
        __syncthreads();
    }
    int run = part[t] - s;   // exclusive prefix
    for (int i = 0; i < 49; i++) {
        int idx = base + i;
        if (idx < NN) {
            g_rowptr[idx] = run;
            run += g_cnt[idx];
        }
    }
    if (t == 1023) g_rowptr[NN] = EE;
}

__global__ void __launch_bounds__(256) fill_kernel(const int* __restrict__ edge)
{
    int i = blockIdx.x * 256 + threadIdx.x;
    if (i >= EE / 8) return;
    int4 s0 = __ldg(reinterpret_cast<const int4*>(edge) + 2 * i);
    int4 s1 = __ldg(reinterpret_cast<const int4*>(edge) + 2 * i + 1);
    int4 d0 = __ldg(reinterpret_cast<const int4*>(edge + EE) + 2 * i);
    int4 d1 = __ldg(reinterpret_cast<const int4*>(edge + EE) + 2 * i + 1);
    int4 o0 = *reinterpret_cast<const int4*>(g_eoff + 8 * i);
    int4 o1 = *reinterpret_cast<const int4*>(g_eoff + 8 * i + 4);
    g_esrc[__ldg(g_rowptr + d0.x) + o0.x] = s0.x;
    g_esrc[__ldg(g_rowptr + d0.y) + o0.y] = s0.y;
    g_esrc[__ldg(g_rowptr + d0.z) + o0.z] = s0.z;
    g_esrc[__ldg(g_rowptr + d0.w) + o0.w] = s0.w;
    g_esrc[__ldg(g_rowptr + d1.x) + o1.x] = s1.x;
    g_esrc[__ldg(g_rowptr + d1.y) + o1.y] = s1.y;
    g_esrc[__ldg(g_rowptr + d1.z) + o1.z] = s1.z;
    g_esrc[__ldg(g_rowptr + d1.w) + o1.w] = s1.w;
}

// ---------- gather aggregation (warp per node, fp32 in/accum, fp16 out) -----
__global__ void __launch_bounds__(256) gather_kernel()
{
    int node = blockIdx.x * 8 + (threadIdx.x >> 5);
    int lane = threadIdx.x & 31;
    int start = __ldg(g_rowptr + node);
    int end   = __ldg(g_rowptr + node + 1);
    float4 a = make_float4(0.f, 0.f, 0.f, 0.f);
    int i = start;
    for (; i + 3 < end; i += 4) {
        int s0 = __ldg(g_esrc + i);
        int s1 = __ldg(g_esrc + i + 1);
        int s2 = __ldg(g_esrc + i + 2);
        int s3 = __ldg(g_esrc + i + 3);
        float4 v0 = ld4(g_x + (long long)s0 * DD + lane * 4);
        float4 v1 = ld4(g_x + (long long)s1 * DD + lane * 4);
        float4 v2 = ld4(g_x + (long long)s2 * DD + lane * 4);
        float4 v3 = ld4(g_x + (long long)s3 * DD + lane * 4);
        a.x += v0.x + v1.x + v2.x + v3.x;
        a.y += v0.y + v1.y + v2.y + v3.y;
        a.z += v0.z + v1.z + v2.z + v3.z;
        a.w += v0.w + v1.w + v2.w + v3.w;
    }
    for (; i < end; i++) {
        int s0 = __ldg(g_esrc + i);
        float4 v0 = ld4(g_x + (long long)s0 * DD + lane * 4);
        a.x += v0.x; a.y += v0.y; a.z += v0.z; a.w += v0.w;
    }
    *reinterpret_cast<uint2*>(g_a16 + (long long)node * DD + lane * 4) =
        make_uint2(pack_h2(a.x, a.y), pack_h2(a.z, a.w));
}

// ---------------- weight convert + transpose (once per launch) ---------------
__global__ void __launch_bounds__(256) split_w_kernel(
    const float* __restrict__ Wl, const float* __restrict__ Wr)
{
    int idx = blockIdx.x * 256 + threadIdx.x;       // 3*128*128 = 49152
    if (idx >= 3 * DD * DD) return;
    int l = idx / (DD * DD);
    int k = (idx / DD) % DD;
    int n = idx % DD;
    int dst = l * DD * DD + n * DD + k;             // transposed [l][n][k]
    float wl = Wl[idx];
    __half h = __float2half_rn(wl);
    g_Wlh[dst] = h;
    g_Wll[dst] = __float2half_rn(wl - __half2float(h));
    g_Wr16[dst] = __float2half_rn(Wr[idx]);
}

// ---------------- embedding + LayerNorm (writes fp32 + fp16) ----------------
__global__ void __launch_bounds__(256) embed_ln_kernel(
    const float* __restrict__ node_emb, const int* __restrict__ pos,
    const float* __restrict__ pos_table, const float* __restrict__ gamma,
    const float* __restrict__ beta)
{
    int row  = blockIdx.x * 8 + (threadIdx.x >> 5);
    int lane = threadIdx.x & 31;
    int p = __ldg(pos + row);
    float4 a  = ld4(node_emb + (long long)row * DD + lane * 4);
    float4 pe = ld4(pos_table + (long long)p * DD + lane * 4);
    float v0 = a.x * SQRTD + pe.x;
    float v1 = a.y * SQRTD + pe.y;
    float v2 = a.z * SQRTD + pe.z;
    float v3 = a.w * SQRTD + pe.w;
    float s  = v0 + v1 + v2 + v3;
    float sq = v0*v0 + v1*v1 + v2*v2 + v3*v3;
    #pragma unroll
    for (int off = 16; off; off >>= 1) {
        s  += __shfl_xor_sync(0xffffffffu, s,  off);
        sq += __shfl_xor_sync(0xffffffffu, sq, off);
    }
    float mean = s * (1.0f / DD);
    float var  = sq * (1.0f / DD) - mean * mean;
    float rstd = rsqrtf(var + EPS);
    float4 g = ld4(gamma + lane * 4);
    float4 b = ld4(beta  + lane * 4);
    float4 o;
    o.x = (v0 - mean) * rstd * g.x + b.x;
    o.y = (v1 - mean) * rstd * g.y + b.y;
    o.z = (v2 - mean) * rstd * g.z + b.z;
    o.w = (v3 - mean) * rstd * g.w + b.w;
    long long base = (long long)row * DD + lane * 4;
    *reinterpret_cast<float4*>(g_x + base) = o;
    *reinterpret_cast<uint2*>(g_x16 + base) =
        make_uint2(pack_h2(o.x, o.y), pack_h2(o.z, o.w));
}

// ---------------- tensor-core dual GEMM + bias + ReLU + residual + LN --------
// 3-pass fp16: agg16*Wlh + agg16*Wll (Wl exact 2-limb) + x16*Wr16.
// 11 warps / 352 threads, 176-row tile, grid 296 = exactly 2 waves.
// 3 fp16 weight matrices persistent in smem (68-word padded stride,
// conflict-free). A/X fragments loaded fp16 from global (L2-hot), dbl-buffered.
__global__ void __launch_bounds__(352) sage_mma_kernel(
    const float* __restrict__ bl, const float* __restrict__ gamma,
    const float* __restrict__ beta, int layer, float* __restrict__ out_opt)
{
    extern __shared__ __align__(16) u32 smem[];   // 3 * 8704 words = 102 KB

    int tid  = threadIdx.x;
    int w    = tid >> 5;
    int lane = tid & 31;
    int g    = lane >> 2;        // 0..7
    int c    = lane & 3;         // 0..3
    int row0 = blockIdx.x * 176;
    long long woff = (long long)layer * DD * DD;

    // ---- load 3 fp16 weight matrices into smem once ----
    {
        const __half* wsrc[3] = { g_Wlh + woff, g_Wll + woff, g_Wr16 + woff };
        #pragma unroll
        for (int m = 0; m < 3; m++) {
            const uint4* s = reinterpret_cast<const uint4*>(wsrc[m]);  // 16/row
            uint4* d = reinterpret_cast<uint4*>(smem) + m * 2176;      // 17/row
            for (int i = tid; i < 2048; i += 352) {
                int n = i >> 4, c4 = i & 15;
                d[n * 17 + c4] = s[i];
            }
        }
    }
    __syncthreads();

    float acc[16][4];
    #pragma unroll
    for (int t = 0; t < 16; t++)
        #pragma unroll
        for (int j = 0; j < 4; j++) acc[t][j] = 0.f;

    int r1 = row0 + w * 16 + g;
    const u32* pa = reinterpret_cast<const u32*>(g_a16) + (long long)r1 * 64;
    const u32* px = reinterpret_cast<const u32*>(g_x16) + (long long)r1 * 64;

    // double-buffered fp16 A/X fragments (row stride 64 words; +8 rows = +512)
    u32 Aa[2][4], Xx[2][4];
    {
        int kw = c;
        Aa[0][0] = pa[kw]; Aa[0][1] = pa[512 + kw]; Aa[0][2] = pa[kw + 4]; Aa[0][3] = pa[512 + kw + 4];
        Xx[0][0] = px[kw]; Xx[0][1] = px[512 + kw]; Xx[0][2] = px[kw + 4]; Xx[0][3] = px[512 + kw + 4];
    }

    #pragma unroll
    for (int ks = 0; ks < 8; ks++) {
        int cur = ks & 1, nxt = cur ^ 1;
        if (ks < 7) {
            int kw = (ks + 1) * 8 + c;
            Aa[nxt][0] = pa[kw]; Aa[nxt][1] = pa[512 + kw]; Aa[nxt][2] = pa[kw + 4]; Aa[nxt][3] = pa[512 + kw + 4];
            Xx[nxt][0] = px[kw]; Xx[nxt][1] = px[512 + kw]; Xx[nxt][2] = px[kw + 4]; Xx[nxt][3] = px[512 + kw + 4];
        }
        int kwb = ks * 8 + c;
        #pragma unroll
        for (int t = 0; t < 16; t++) {
            int b0 = (t * 8 + g) * 68 + kwb;
            u32 wlh[2] = { smem[b0],         smem[b0 + 4] };
            u32 wll[2] = { smem[8704 + b0],  smem[8704 + b0 + 4] };
            u32 wr[2]  = { smem[17408 + b0], smem[17408 + b0 + 4] };
            mma16816h(acc[t], Aa[cur], wlh);
            mma16816h(acc[t], Aa[cur], wll);
            mma16816h(acc[t], Xx[cur], wr);
        }
    }

    // ---- epilogue: bias + relu + residual + LayerNorm ----
    int r2 = r1 + 8;
    float v[16][4];
    #pragma unroll
    for (int t = 0; t < 16; t++) {
        int col = t * 8 + c * 2;
        float2 bb = *reinterpret_cast<const float2*>(bl + col);
        float2 xa = *reinterpret_cast<const float2*>(g_x + (long long)r1 * DD + col);
        float2 xb = *reinterpret_cast<const float2*>(g_x + (long long)r2 * DD + col);
        v[t][0] = fmaxf(acc[t][0] + bb.x, 0.f) + xa.x;
        v[t][1] = fmaxf(acc[t][1] + bb.y, 0.f) + xa.y;
        v[t][2] = fmaxf(acc[t][2] + bb.x, 0.f) + xb.x;
        v[t][3] = fmaxf(acc[t][3] + bb.y, 0.f) + xb.y;
    }
    float s1 = 0.f, q1 = 0.f, s2 = 0.f, q2 = 0.f;
    #pragma unroll
    for (int t = 0; t < 16; t++) {
        s1 += v[t][0] + v[t][1];
        q1 += v[t][0] * v[t][0] + v[t][1] * v[t][1];
        s2 += v[t][2] + v[t][3];
        q2 += v[t][2] * v[t][2] + v[t][3] * v[t][3];
    }
    #pragma unroll
    for (int m = 1; m <= 2; m <<= 1) {
        s1 += __shfl_xor_sync(0xffffffffu, s1, m);
        q1 += __shfl_xor_sync(0xffffffffu, q1, m);
        s2 += __shfl_xor_sync(0xffffffffu, s2, m);
        q2 += __shfl_xor_sync(0xffffffffu, q2, m);
    }
    float mean1 = s1 * (1.0f / DD);
    float var1  = q1 * (1.0f / DD) - mean1 * mean1;
    float rs1   = rsqrtf(var1 + EPS);
    float mean2 = s2 * (1.0f / DD);
    float var2  = q2 * (1.0f / DD) - mean2 * mean2;
    float rs2   = rsqrtf(var2 + EPS);

    bool final = (out_opt != nullptr);
    #pragma unroll
    for (int t = 0; t < 16; t++) {
        int col = t * 8 + c * 2;
        float2 gg = *reinterpret_cast<const float2*>(gamma + col);
        float2 be = *reinterpret_cast<const float2*>(beta + col);
        float2 o1, o2;
        o1.x = (v[t][0] - mean1) * rs1 * gg.x + be.x;
        o1.y = (v[t][1] - mean1) * rs1 * gg.y + be.y;
        o2.x = (v[t][2] - mean2) * rs2 * gg.x + be.x;
        o2.y = (v[t][3] - mean2) * rs2 * gg.y + be.y;
        if (final) {
            if (r1 < NN)
                *reinterpret_cast<float2*>(out_opt + (long long)r1 * DD + col) = o1;
            if (r2 < NN)
                *reinterpret_cast<float2*>(out_opt + (long long)r2 * DD + col) = o2;
        } else {
            *reinterpret_cast<float2*>(g_x + (long long)r1 * DD + col) = o1;
            *reinterpret_cast<float2*>(g_x + (long long)r2 * DD + col) = o2;
            *reinterpret_cast<u32*>(g_x16 + (long long)r1 * DD + col) = pack_h2(o1.x, o1.y);
            *reinterpret_cast<u32*>(g_x16 + (long long)r2 * DD + col) = pack_h2(o2.x, o2.y);
        }
    }
}

extern "C" void kernel_launch(void* const* d_in, const int* in_sizes, int n_in,
                              void* d_out, int out_size)
{
    const float* node_emb  = (const float*)d_in[0];
    const int*   pos       = (const int*)  d_in[1];
    const int*   edge      = (const int*)  d_in[2];
    const float* pos_table = (const float*)d_in[3];
    const float* Wl        = (const float*)d_in[4];
    const float* bl        = (const float*)d_in[5];
    const float* Wr        = (const float*)d_in[6];
    const float* emb_g     = (const float*)d_in[7];
    const float* emb_b     = (const float*)d_in[8];
    const float* hid_g     = (const float*)d_in[9];
    const float* hid_b     = (const float*)d_in[10];
    float* out = (float*)d_out;

    const int SMEM = 3 * 8704 * 4;  // 104448 bytes
    cudaFuncSetAttribute(sage_mma_kernel,
                         cudaFuncAttributeMaxDynamicSharedMemorySize, SMEM);

    // CSR build (once per launch)
    zero_cnt_kernel<<<196, 256>>>();
    hist_off_kernel<<<(EE / 8 + 255) / 256, 256>>>(edge);
    scan_kernel<<<1, 1024>>>();
    fill_kernel<<<(EE / 8 + 255) / 256, 256>>>(edge);

    split_w_kernel<<<192, 256>>>(Wl, Wr);
    embed_ln_kernel<<<NN / 8, 256>>>(node_emb, pos, pos_table, emb_g, emb_b);

    const int gath_grid = NN / 8;             // 6250
    const int gemm_grid = NP / 176;           // 296

    for (int l = 0; l < 3; l++) {
        gather_kernel<<<gath_grid, 256>>>();
        float* outp = (l == 2) ? out : nullptr;
        sage_mma_kernel<<<gemm_grid, 352, SMEM>>>(
            bl + l * DD, hid_g + l * DD, hid_b + l * DD, l, outp);
    }
}

// round 15
// speedup vs baseline: 1.0582x; 1.0582x over previous
#include <cuda_runtime.h>
#include <cuda_fp16.h>

#define NN 50000
#define NP 52096          // padded rows (296*176)
#define EE 800000
#define DD 128
#define EPS 1e-5f
#define SQRTD 11.313708498984761f

typedef unsigned int u32;

__device__ __align__(16) float g_x[(long long)NP * DD];
__device__ __align__(16) __half g_x16[(long long)NP * DD];   // fp16 mirror of x
__device__ __align__(16) __half g_a16[(long long)NP * DD];   // fp16 aggregation
// weights, transposed [layer][n][k]: Wl as fp16 hi/lo pair (exact-ish), Wr fp16
__device__ __align__(16) __half g_Wlh[3 * DD * DD];
__device__ __align__(16) __half g_Wll[3 * DD * DD];
__device__ __align__(16) __half g_Wr16[3 * DD * DD];
// CSR (by dst)
__device__ int g_cnt[NN];
__device__ int g_rowptr[NN + 1];
__device__ __align__(16) int g_eoff[EE];
__device__ int g_esrc[EE];

__device__ __forceinline__ float4 ld4(const float* __restrict__ p) {
    return *reinterpret_cast<const float4*>(p);
}

__device__ __forceinline__ u32 pack_h2(float a, float b) {
    __half2 h = __floats2half2_rn(a, b);
    return *reinterpret_cast<u32*>(&h);
}

__device__ __forceinline__ void mma16816h(float* d, const u32* a, const u32* b) {
    asm volatile(
        "mma.sync.aligned.m16n8k16.row.col.f32.f16.f16.f32 "
        "{%0,%1,%2,%3}, {%4,%5,%6,%7}, {%8,%9}, {%0,%1,%2,%3};"
        : "+f"(d[0]), "+f"(d[1]), "+f"(d[2]), "+f"(d[3])
        : "r"(a[0]), "r"(a[1]), "r"(a[2]), "r"(a[3]), "r"(b[0]), "r"(b[1]));
}

// ---------------- CSR build ----------------
__global__ void __launch_bounds__(256) zero_cnt_kernel()
{
    int i = blockIdx.x * 256 + threadIdx.x;
    if (i < NN) g_cnt[i] = 0;
}

__global__ void __launch_bounds__(256) hist_off_kernel(const int* __restrict__ edge)
{
    int i = blockIdx.x * 256 + threadIdx.x;
    if (i >= EE / 8) return;
    int4 d0 = __ldg(reinterpret_cast<const int4*>(edge + EE) + 2 * i);
    int4 d1 = __ldg(reinterpret_cast<const int4*>(edge + EE) + 2 * i + 1);
    int4 o0, o1;
    o0.x = atomicAdd(&g_cnt[d0.x], 1);
    o0.y = atomicAdd(&g_cnt[d0.y], 1);
    o0.z = atomicAdd(&g_cnt[d0.z], 1);
    o0.w = atomicAdd(&g_cnt[d0.w], 1);
    o1.x = atomicAdd(&g_cnt[d1.x], 1);
    o1.y = atomicAdd(&g_cnt[d1.y], 1);
    o1.z = atomicAdd(&g_cnt[d1.z], 1);
    o1.w = atomicAdd(&g_cnt[d1.w], 1);
    reinterpret_cast<int4*>(g_eoff)[2 * i]     = o0;
    reinterpret_cast<int4*>(g_eoff)[2 * i + 1] = o1;
}

__global__ void __launch_bounds__(1024) scan_kernel()
{
    __shared__ int part[1024];
    int t = threadIdx.x;
    int base = t * 49;
    int s = 0;
    for (int i = 0; i < 49; i++) {
        int idx = base + i;
        if (idx < NN) s += g_cnt[idx];
    }
    part[t] = s;
    __syncthreads();
    for (int off = 1; off < 1024; off <<= 1) {
        int add = (t >= off) ? part[t - off] : 0;
        __syncthreads();
        part[t] += add;
        __syncthreads();
    }
    int run = part[t] - s;   // exclusive prefix
    for (int i = 0; i < 49; i++) {
        int idx = base + i;
        if (idx < NN) {
            g_rowptr[idx] = run;
            run += g_cnt[idx];
        }
    }
    if (t == 1023) g_rowptr[NN] = EE;
}

__global__ void __launch_bounds__(256) fill_kernel(const int* __restrict__ edge)
{
    int i = blockIdx.x * 256 + threadIdx.x;
    if (i >= EE / 8) return;
    int4 s0 = __ldg(reinterpret_cast<const int4*>(edge) + 2 * i);
    int4 s1 = __ldg(reinterpret_cast<const int4*>(edge) + 2 * i + 1);
    int4 d0 = __ldg(reinterpret_cast<const int4*>(edge + EE) + 2 * i);
    int4 d1 = __ldg(reinterpret_cast<const int4*>(edge + EE) + 2 * i + 1);
    int4 o0 = *reinterpret_cast<const int4*>(g_eoff + 8 * i);
    int4 o1 = *reinterpret_cast<const int4*>(g_eoff + 8 * i + 4);
    g_esrc[__ldg(g_rowptr + d0.x) + o0.x] = s0.x;
    g_esrc[__ldg(g_rowptr + d0.y) + o0.y] = s0.y;
    g_esrc[__ldg(g_rowptr + d0.z) + o0.z] = s0.z;
    g_esrc[__ldg(g_rowptr + d0.w) + o0.w] = s0.w;
    g_esrc[__ldg(g_rowptr + d1.x) + o1.x] = s1.x;
    g_esrc[__ldg(g_rowptr + d1.y) + o1.y] = s1.y;
    g_esrc[__ldg(g_rowptr + d1.z) + o1.z] = s1.z;
    g_esrc[__ldg(g_rowptr + d1.w) + o1.w] = s1.w;
}

// ------- gather aggregation (warp per node, fp16 in, fp32 accum, fp16 out) ---
__global__ void __launch_bounds__(256) gather_kernel()
{
    int node = blockIdx.x * 8 + (threadIdx.x >> 5);
    int lane = threadIdx.x & 31;
    int start = __ldg(g_rowptr + node);
    int end   = __ldg(g_rowptr + node + 1);
    float4 a = make_float4(0.f, 0.f, 0.f, 0.f);
    int i = start;
    for (; i + 3 < end; i += 4) {
        int s0 = __ldg(g_esrc + i);
        int s1 = __ldg(g_esrc + i + 1);
        int s2 = __ldg(g_esrc + i + 2);
        int s3 = __ldg(g_esrc + i + 3);
        uint2 v0 = *reinterpret_cast<const uint2*>(g_x16 + (long long)s0 * DD + lane * 4);
        uint2 v1 = *reinterpret_cast<const uint2*>(g_x16 + (long long)s1 * DD + lane * 4);
        uint2 v2 = *reinterpret_cast<const uint2*>(g_x16 + (long long)s2 * DD + lane * 4);
        uint2 v3 = *reinterpret_cast<const uint2*>(g_x16 + (long long)s3 * DD + lane * 4);
        float2 p;
        p = __half22float2(*reinterpret_cast<__half2*>(&v0.x)); a.x += p.x; a.y += p.y;
        p = __half22float2(*reinterpret_cast<__half2*>(&v0.y)); a.z += p.x; a.w += p.y;
        p = __half22float2(*reinterpret_cast<__half2*>(&v1.x)); a.x += p.x; a.y += p.y;
        p = __half22float2(*reinterpret_cast<__half2*>(&v1.y)); a.z += p.x; a.w += p.y;
        p = __half22float2(*reinterpret_cast<__half2*>(&v2.x)); a.x += p.x; a.y += p.y;
        p = __half22float2(*reinterpret_cast<__half2*>(&v2.y)); a.z += p.x; a.w += p.y;
        p = __half22float2(*reinterpret_cast<__half2*>(&v3.x)); a.x += p.x; a.y += p.y;
        p = __half22float2(*reinterpret_cast<__half2*>(&v3.y)); a.z += p.x; a.w += p.y;
    }
    for (; i < end; i++) {
        int s0 = __ldg(g_esrc + i);
        uint2 v0 = *reinterpret_cast<const uint2*>(g_x16 + (long long)s0 * DD + lane * 4);
        float2 p;
        p = __half22float2(*reinterpret_cast<__half2*>(&v0.x)); a.x += p.x; a.y += p.y;
        p = __half22float2(*reinterpret_cast<__half2*>(&v0.y)); a.z += p.x; a.w += p.y;
    }
    *reinterpret_cast<uint2*>(g_a16 + (long long)node * DD + lane * 4) =
        make_uint2(pack_h2(a.x, a.y), pack_h2(a.z, a.w));
}

// ---------------- weight convert + transpose (once per launch) ---------------
__global__ void __launch_bounds__(256) split_w_kernel(
    const float* __restrict__ Wl, const float* __restrict__ Wr)
{
    int idx = blockIdx.x * 256 + threadIdx.x;       // 3*128*128 = 49152
    if (idx >= 3 * DD * DD) return;
    int l = idx / (DD * DD);
    int k = (idx / DD) % DD;
    int n = idx % DD;
    int dst = l * DD * DD + n * DD + k;             // transposed [l][n][k]
    float wl = Wl[idx];
    __half h = __float2half_rn(wl);
    g_Wlh[dst] = h;
    g_Wll[dst] = __float2half_rn(wl - __half2float(h));
    g_Wr16[dst] = __float2half_rn(Wr[idx]);
}

// ---------------- embedding + LayerNorm (writes fp32 + fp16) ----------------
__global__ void __launch_bounds__(256) embed_ln_kernel(
    const float* __restrict__ node_emb, const int* __restrict__ pos,
    const float* __restrict__ pos_table, const float* __restrict__ gamma,
    const float* __restrict__ beta)
{
    int row  = blockIdx.x * 8 + (threadIdx.x >> 5);
    int lane = threadIdx.x & 31;
    int p = __ldg(pos + row);
    float4 a  = ld4(node_emb + (long long)row * DD + lane * 4);
    float4 pe = ld4(pos_table + (long long)p * DD + lane * 4);
    float v0 = a.x * SQRTD + pe.x;
    float v1 = a.y * SQRTD + pe.y;
    float v2 = a.z * SQRTD + pe.z;
    float v3 = a.w * SQRTD + pe.w;
    float s  = v0 + v1 + v2 + v3;
    float sq = v0*v0 + v1*v1 + v2*v2 + v3*v3;
    #pragma unroll
    for (int off = 16; off; off >>= 1) {
        s  += __shfl_xor_sync(0xffffffffu, s,  off);
        sq += __shfl_xor_sync(0xffffffffu, sq, off);
    }
    float mean = s * (1.0f / DD);
    float var  = sq * (1.0f / DD) - mean * mean;
    float rstd = rsqrtf(var + EPS);
    float4 g = ld4(gamma + lane * 4);
    float4 b = ld4(beta  + lane * 4);
    float4 o;
    o.x = (v0 - mean) * rstd * g.x + b.x;
    o.y = (v1 - mean) * rstd * g.y + b.y;
    o.z = (v2 - mean) * rstd * g.z + b.z;
    o.w = (v3 - mean) * rstd * g.w + b.w;
    long long base = (long long)row * DD + lane * 4;
    *reinterpret_cast<float4*>(g_x + base) = o;
    *reinterpret_cast<uint2*>(g_x16 + base) =
        make_uint2(pack_h2(o.x, o.y), pack_h2(o.z, o.w));
}

// ---------------- tensor-core dual GEMM + bias + ReLU + residual + LN --------
// 3-pass fp16: agg16*Wlh + agg16*Wll (Wl exact 2-limb) + x16*Wr16.
// 11 warps / 352 threads, 176-row tile, grid 296 = exactly 2 waves.
// 3 fp16 weight matrices persistent in smem (68-word padded stride,
// conflict-free). A/X fragments loaded fp16 from global (L2-hot), dbl-buffered.
__global__ void __launch_bounds__(352) sage_mma_kernel(
    const float* __restrict__ bl, const float* __restrict__ gamma,
    const float* __restrict__ beta, int layer, float* __restrict__ out_opt)
{
    extern __shared__ __align__(16) u32 smem[];   // 3 * 8704 words = 102 KB

    int tid  = threadIdx.x;
    int w    = tid >> 5;
    int lane = tid & 31;
    int g    = lane >> 2;        // 0..7
    int c    = lane & 3;         // 0..3
    int row0 = blockIdx.x * 176;
    long long woff = (long long)layer * DD * DD;

    // ---- load 3 fp16 weight matrices into smem once ----
    {
        const __half* wsrc[3] = { g_Wlh + woff, g_Wll + woff, g_Wr16 + woff };
        #pragma unroll
        for (int m = 0; m < 3; m++) {
            const uint4* s = reinterpret_cast<const uint4*>(wsrc[m]);  // 16/row
            uint4* d = reinterpret_cast<uint4*>(smem) + m * 2176;      // 17/row
            for (int i = tid; i < 2048; i += 352) {
                int n = i >> 4, c4 = i & 15;
                d[n * 17 + c4] = s[i];
            }
        }
    }
    __syncthreads();

    float acc[16][4];
    #pragma unroll
    for (int t = 0; t < 16; t++)
        #pragma unroll
        for (int j = 0; j < 4; j++) acc[t][j] = 0.f;

    int r1 = row0 + w * 16 + g;
    const u32* pa = reinterpret_cast<const u32*>(g_a16) + (long long)r1 * 64;
    const u32* px = reinterpret_cast<const u32*>(g_x16) + (long long)r1 * 64;

    // double-buffered fp16 A/X fragments (row stride 64 words; +8 rows = +512)
    u32 Aa[2][4], Xx[2][4];
    {
        int kw = c;
        Aa[0][0] = pa[kw]; Aa[0][1] = pa[512 + kw]; Aa[0][2] = pa[kw + 4]; Aa[0][3] = pa[512 + kw + 4];
        Xx[0][0] = px[kw]; Xx[0][1] = px[512 + kw]; Xx[0][2] = px[kw + 4]; Xx[0][3] = px[512 + kw + 4];
    }

    #pragma unroll
    for (int ks = 0; ks < 8; ks++) {
        int cur = ks & 1, nxt = cur ^ 1;
        if (ks < 7) {
            int kw = (ks + 1) * 8 + c;
            Aa[nxt][0] = pa[kw]; Aa[nxt][1] = pa[512 + kw]; Aa[nxt][2] = pa[kw + 4]; Aa[nxt][3] = pa[512 + kw + 4];
            Xx[nxt][0] = px[kw]; Xx[nxt][1] = px[512 + kw]; Xx[nxt][2] = px[kw + 4]; Xx[nxt][3] = px[512 + kw + 4];
        }
        int kwb = ks * 8 + c;
        #pragma unroll
        for (int t = 0; t < 16; t++) {
            int b0 = (t * 8 + g) * 68 + kwb;
            u32 wlh[2] = { smem[b0],         smem[b0 + 4] };
            u32 wll[2] = { smem[8704 + b0],  smem[8704 + b0 + 4] };
            u32 wr[2]  = { smem[17408 + b0], smem[17408 + b0 + 4] };
            mma16816h(acc[t], Aa[cur], wlh);
            mma16816h(acc[t], Aa[cur], wll);
            mma16816h(acc[t], Xx[cur], wr);
        }
    }

    // ---- epilogue: bias + relu + residual + LayerNorm ----
    int r2 = r1 + 8;
    float v[16][4];
    #pragma unroll
    for (int t = 0; t < 16; t++) {
        int col = t * 8 + c * 2;
        float2 bb = *reinterpret_cast<const float2*>(bl + col);
        float2 xa = *reinterpret_cast<const float2*>(g_x + (long long)r1 * DD + col);
        float2 xb = *reinterpret_cast<const float2*>(g_x + (long long)r2 * DD + col);
        v[t][0] = fmaxf(acc[t][0] + bb.x, 0.f) + xa.x;
        v[t][1] = fmaxf(acc[t][1] + bb.y, 0.f) + xa.y;
        v[t][2] = fmaxf(acc[t][2] + bb.x, 0.f) + xb.x;
        v[t][3] = fmaxf(acc[t][3] + bb.y, 0.f) + xb.y;
    }
    float s1 = 0.f, q1 = 0.f, s2 = 0.f, q2 = 0.f;
    #pragma unroll
    for (int t = 0; t < 16; t++) {
        s1 += v[t][0] + v[t][1];
        q1 += v[t][0] * v[t][0] + v[t][1] * v[t][1];
        s2 += v[t][2] + v[t][3];
        q2 += v[t][2] * v[t][2] + v[t][3] * v[t][3];
    }
    #pragma unroll
    for (int m = 1; m <= 2; m <<= 1) {
        s1 += __shfl_xor_sync(0xffffffffu, s1, m);
        q1 += __shfl_xor_sync(0xffffffffu, q1, m);
        s2 += __shfl_xor_sync(0xffffffffu, s2, m);
        q2 += __shfl_xor_sync(0xffffffffu, q2, m);
    }
    float mean1 = s1 * (1.0f / DD);
    float var1  = q1 * (1.0f / DD) - mean1 * mean1;
    float rs1   = rsqrtf(var1 + EPS);
    float mean2 = s2 * (1.0f / DD);
    float var2  = q2 * (1.0f / DD) - mean2 * mean2;
    float rs2   = rsqrtf(var2 + EPS);

    bool final = (out_opt != nullptr);
    #pragma unroll
    for (int t = 0; t < 16; t++) {
        int col = t * 8 + c * 2;
        float2 gg = *reinterpret_cast<const float2*>(gamma + col);
        float2 be = *reinterpret_cast<const float2*>(beta + col);
        float2 o1, o2;
        o1.x = (v[t][0] - mean1) * rs1 * gg.x + be.x;
        o1.y = (v[t][1] - mean1) * rs1 * gg.y + be.y;
        o2.x = (v[t][2] - mean2) * rs2 * gg.x + be.x;
        o2.y = (v[t][3] - mean2) * rs2 * gg.y + be.y;
        if (final) {
            if (r1 < NN)
                *reinterpret_cast<float2*>(out_opt + (long long)r1 * DD + col) = o1;
            if (r2 < NN)
                *reinterpret_cast<float2*>(out_opt + (long long)r2 * DD + col) = o2;
        } else {
            *reinterpret_cast<float2*>(g_x + (long long)r1 * DD + col) = o1;
            *reinterpret_cast<float2*>(g_x + (long long)r2 * DD + col) = o2;
            *reinterpret_cast<u32*>(g_x16 + (long long)r1 * DD + col) = pack_h2(o1.x, o1.y);
            *reinterpret_cast<u32*>(g_x16 + (long long)r2 * DD + col) = pack_h2(o2.x, o2.y);
        }
    }
}

extern "C" void kernel_launch(void* const* d_in, const int* in_sizes, int n_in,
                              void* d_out, int out_size)
{
    const float* node_emb  = (const float*)d_in[0];
    const int*   pos       = (const int*)  d_in[1];
    const int*   edge      = (const int*)  d_in[2];
    const float* pos_table = (const float*)d_in[3];
    const float* Wl        = (const float*)d_in[4];
    const float* bl        = (const float*)d_in[5];
    const float* Wr        = (const float*)d_in[6];
    const float* emb_g     = (const float*)d_in[7];
    const float* emb_b     = (const float*)d_in[8];
    const float* hid_g     = (const float*)d_in[9];
    const float* hid_b     = (const float*)d_in[10];
    float* out = (float*)d_out;

    const int SMEM = 3 * 8704 * 4;  // 104448 bytes
    cudaFuncSetAttribute(sage_mma_kernel,
                         cudaFuncAttributeMaxDynamicSharedMemorySize, SMEM);

    // CSR build (once per launch)
    zero_cnt_kernel<<<196, 256>>>();
    hist_off_kernel<<<(EE / 8 + 255) / 256, 256>>>(edge);
    scan_kernel<<<1, 1024>>>();
    fill_kernel<<<(EE / 8 + 255) / 256, 256>>>(edge);

    split_w_kernel<<<192, 256>>>(Wl, Wr);
    embed_ln_kernel<<<NN / 8, 256>>>(node_emb, pos, pos_table, emb_g, emb_b);

    const int gath_grid = NN / 8;             // 6250
    const int gemm_grid = NP / 176;           // 296

    for (int l = 0; l < 3; l++) {
        gather_kernel<<<gath_grid, 256>>>();
        float* outp = (l == 2) ? out : nullptr;
        sage_mma_kernel<<<gemm_grid, 352, SMEM>>>(
            bl + l * DD, hid_g + l * DD, hid_b + l * DD, l, outp);
    }
}

// round 16
// speedup vs baseline: 1.1477x; 1.0847x over previous
#include <cuda_runtime.h>
#include <cuda_fp16.h>

#define NN 50000
#define NP 52096          // padded rows (296*176)
#define EE 800000
#define DD 128
#define EPS 1e-5f
#define SQRTD 11.313708498984761f

typedef unsigned int u32;

__device__ __align__(16) float g_x[(long long)NP * DD];
__device__ __align__(16) __half g_x16[(long long)NP * DD];   // fp16 mirror of x
__device__ __align__(16) __half g_a16[(long long)NP * DD];   // fp16 aggregation
// weights fp16, transposed [layer][n][k]
__device__ __align__(16) __half g_Wl16[3 * DD * DD];
__device__ __align__(16) __half g_Wr16[3 * DD * DD];
// CSR (by dst)
__device__ int g_cnt[NN];
__device__ int g_rowptr[NN + 1];
__device__ __align__(16) int g_eoff[EE];
__device__ int g_esrc[EE];

__device__ __forceinline__ float4 ld4(const float* __restrict__ p) {
    return *reinterpret_cast<const float4*>(p);
}

__device__ __forceinline__ u32 pack_h2(float a, float b) {
    __half2 h = __floats2half2_rn(a, b);
    return *reinterpret_cast<u32*>(&h);
}

__device__ __forceinline__ void mma16816h(float* d, const u32* a, const u32* b) {
    asm volatile(
        "mma.sync.aligned.m16n8k16.row.col.f32.f16.f16.f32 "
        "{%0,%1,%2,%3}, {%4,%5,%6,%7}, {%8,%9}, {%0,%1,%2,%3};"
        : "+f"(d[0]), "+f"(d[1]), "+f"(d[2]), "+f"(d[3])
        : "r"(a[0]), "r"(a[1]), "r"(a[2]), "r"(a[3]), "r"(b[0]), "r"(b[1]));
}

// ---------------- CSR build ----------------
__global__ void __launch_bounds__(256) zero_cnt_kernel()
{
    int i = blockIdx.x * 256 + threadIdx.x;
    if (i < NN) g_cnt[i] = 0;
}

__global__ void __launch_bounds__(256) hist_off_kernel(const int* __restrict__ edge)
{
    int i = blockIdx.x * 256 + threadIdx.x;
    if (i >= EE / 8) return;
    int4 d0 = __ldg(reinterpret_cast<const int4*>(edge + EE) + 2 * i);
    int4 d1 = __ldg(reinterpret_cast<const int4*>(edge + EE) + 2 * i + 1);
    int4 o0, o1;
    o0.x = atomicAdd(&g_cnt[d0.x], 1);
    o0.y = atomicAdd(&g_cnt[d0.y], 1);
    o0.z = atomicAdd(&g_cnt[d0.z], 1);
    o0.w = atomicAdd(&g_cnt[d0.w], 1);
    o1.x = atomicAdd(&g_cnt[d1.x], 1);
    o1.y = atomicAdd(&g_cnt[d1.y], 1);
    o1.z = atomicAdd(&g_cnt[d1.z], 1);
    o1.w = atomicAdd(&g_cnt[d1.w], 1);
    reinterpret_cast<int4*>(g_eoff)[2 * i]     = o0;
    reinterpret_cast<int4*>(g_eoff)[2 * i + 1] = o1;
}

__global__ void __launch_bounds__(1024) scan_kernel()
{
    __shared__ int part[1024];
    int t = threadIdx.x;
    int base = t * 49;
    int s = 0;
    for (int i = 0; i < 49; i++) {
        int idx = base + i;
        if (idx < NN) s += g_cnt[idx];
    }
    part[t] = s;
    __syncthreads();
    for (int off = 1; off < 1024; off <<= 1) {
        int add = (t >= off) ? part[t - off] : 0;
        __syncthreads();
        part[t] += add;
        __syncthreads();
    }
    int run = part[t] - s;   // exclusive prefix
    for (int i = 0; i < 49; i++) {
        int idx = base + i;
        if (idx < NN) {
            g_rowptr[idx] = run;
            run += g_cnt[idx];
        }
    }
    if (t == 1023) g_rowptr[NN] = EE;
}

__global__ void __launch_bounds__(256) fill_kernel(const int* __restrict__ edge)
{
    int i = blockIdx.x * 256 + threadIdx.x;
    if (i >= EE / 8) return;
    int4 s0 = __ldg(reinterpret_cast<const int4*>(edge) + 2 * i);
    int4 s1 = __ldg(reinterpret_cast<const int4*>(edge) + 2 * i + 1);
    int4 d0 = __ldg(reinterpret_cast<const int4*>(edge + EE) + 2 * i);
    int4 d1 = __ldg(reinterpret_cast<const int4*>(edge + EE) + 2 * i + 1);
    int4 o0 = *reinterpret_cast<const int4*>(g_eoff + 8 * i);
    int4 o1 = *reinterpret_cast<const int4*>(g_eoff + 8 * i + 4);
    g_esrc[__ldg(g_rowptr + d0.x) + o0.x] = s0.x;
    g_esrc[__ldg(g_rowptr + d0.y) + o0.y] = s0.y;
    g_esrc[__ldg(g_rowptr + d0.z) + o0.z] = s0.z;
    g_esrc[__ldg(g_rowptr + d0.w) + o0.w] = s0.w;
    g_esrc[__ldg(g_rowptr + d1.x) + o1.x] = s1.x;
    g_esrc[__ldg(g_rowptr + d1.y) + o1.y] = s1.y;
    g_esrc[__ldg(g_rowptr + d1.z) + o1.z] = s1.z;
    g_esrc[__ldg(g_rowptr + d1.w) + o1.w] = s1.w;
}

// ------- gather aggregation (warp per node, fp16 in, fp32 accum, fp16 out) ---
__global__ void __launch_bounds__(256) gather_kernel()
{
    int node = blockIdx.x * 8 + (threadIdx.x >> 5);
    int lane = threadIdx.x & 31;
    int start = __ldg(g_rowptr + node);
    int end   = __ldg(g_rowptr + node + 1);
    float4 a = make_float4(0.f, 0.f, 0.f, 0.f);
    int i = start;
    for (; i + 3 < end; i += 4) {
        int s0 = __ldg(g_esrc + i);
        int s1 = __ldg(g_esrc + i + 1);
        int s2 = __ldg(g_esrc + i + 2);
        int s3 = __ldg(g_esrc + i + 3);
        uint2 v0 = *reinterpret_cast<const uint2*>(g_x16 + (long long)s0 * DD + lane * 4);
        uint2 v1 = *reinterpret_cast<const uint2*>(g_x16 + (long long)s1 * DD + lane * 4);
        uint2 v2 = *reinterpret_cast<const uint2*>(g_x16 + (long long)s2 * DD + lane * 4);
        uint2 v3 = *reinterpret_cast<const uint2*>(g_x16 + (long long)s3 * DD + lane * 4);
        float2 p;
        p = __half22float2(*reinterpret_cast<__half2*>(&v0.x)); a.x += p.x; a.y += p.y;
        p = __half22float2(*reinterpret_cast<__half2*>(&v0.y)); a.z += p.x; a.w += p.y;
        p = __half22float2(*reinterpret_cast<__half2*>(&v1.x)); a.x += p.x; a.y += p.y;
        p = __half22float2(*reinterpret_cast<__half2*>(&v1.y)); a.z += p.x; a.w += p.y;
        p = __half22float2(*reinterpret_cast<__half2*>(&v2.x)); a.x += p.x; a.y += p.y;
        p = __half22float2(*reinterpret_cast<__half2*>(&v2.y)); a.z += p.x; a.w += p.y;
        p = __half22float2(*reinterpret_cast<__half2*>(&v3.x)); a.x += p.x; a.y += p.y;
        p = __half22float2(*reinterpret_cast<__half2*>(&v3.y)); a.z += p.x; a.w += p.y;
    }
    for (; i < end; i++) {
        int s0 = __ldg(g_esrc + i);
        uint2 v0 = *reinterpret_cast<const uint2*>(g_x16 + (long long)s0 * DD + lane * 4);
        float2 p;
        p = __half22float2(*reinterpret_cast<__half2*>(&v0.x)); a.x += p.x; a.y += p.y;
        p = __half22float2(*reinterpret_cast<__half2*>(&v0.y)); a.z += p.x; a.w += p.y;
    }
    *reinterpret_cast<uint2*>(g_a16 + (long long)node * DD + lane * 4) =
        make_uint2(pack_h2(a.x, a.y), pack_h2(a.z, a.w));
}

// ---------------- weight convert + transpose (once per launch) ---------------
__global__ void __launch_bounds__(256) split_w_kernel(
    const float* __restrict__ Wl, const float* __restrict__ Wr)
{
    int idx = blockIdx.x * 256 + threadIdx.x;       // 3*128*128 = 49152
    if (idx >= 3 * DD * DD) return;
    int l = idx / (DD * DD);
    int k = (idx / DD) % DD;
    int n = idx % DD;
    int dst = l * DD * DD + n * DD + k;             // transposed [l][n][k]
    g_Wl16[dst] = __float2half_rn(Wl[idx]);
    g_Wr16[dst] = __float2half_rn(Wr[idx]);
}

// ---------------- embedding + LayerNorm (writes fp32 + fp16) ----------------
__global__ void __launch_bounds__(256) embed_ln_kernel(
    const float* __restrict__ node_emb, const int* __restrict__ pos,
    const float* __restrict__ pos_table, const float* __restrict__ gamma,
    const float* __restrict__ beta)
{
    int row  = blockIdx.x * 8 + (threadIdx.x >> 5);
    int lane = threadIdx.x & 31;
    int p = __ldg(pos + row);
    float4 a  = ld4(node_emb + (long long)row * DD + lane * 4);
    float4 pe = ld4(pos_table + (long long)p * DD + lane * 4);
    float v0 = a.x * SQRTD + pe.x;
    float v1 = a.y * SQRTD + pe.y;
    float v2 = a.z * SQRTD + pe.z;
    float v3 = a.w * SQRTD + pe.w;
    float s  = v0 + v1 + v2 + v3;
    float sq = v0*v0 + v1*v1 + v2*v2 + v3*v3;
    #pragma unroll
    for (int off = 16; off; off >>= 1) {
        s  += __shfl_xor_sync(0xffffffffu, s,  off);
        sq += __shfl_xor_sync(0xffffffffu, sq, off);
    }
    float mean = s * (1.0f / DD);
    float var  = sq * (1.0f / DD) - mean * mean;
    float rstd = rsqrtf(var + EPS);
    float4 g = ld4(gamma + lane * 4);
    float4 b = ld4(beta  + lane * 4);
    float4 o;
    o.x = (v0 - mean) * rstd * g.x + b.x;
    o.y = (v1 - mean) * rstd * g.y + b.y;
    o.z = (v2 - mean) * rstd * g.z + b.z;
    o.w = (v3 - mean) * rstd * g.w + b.w;
    long long base = (long long)row * DD + lane * 4;
    *reinterpret_cast<float4*>(g_x + base) = o;
    *reinterpret_cast<uint2*>(g_x16 + base) =
        make_uint2(pack_h2(o.x, o.y), pack_h2(o.z, o.w));
}

// ---------------- tensor-core dual GEMM + bias + ReLU + residual + LN --------
// 2-pass fp16: a16*Wl16 + x16*Wr16 — minimal issue count (4 LDS + 2 HMMA / t).
// 11 warps / 352 threads, 176-row tile, grid 296 = exactly 2 waves.
// 2 fp16 weight matrices persistent in smem (68-word padded stride,
// conflict-free). A/X fragments loaded fp16 from global (L2-hot), dbl-buffered.
__global__ void __launch_bounds__(352) sage_mma_kernel(
    const float* __restrict__ bl, const float* __restrict__ gamma,
    const float* __restrict__ beta, int layer, float* __restrict__ out_opt)
{
    extern __shared__ __align__(16) u32 smem[];   // 2 * 8704 words = 68 KB

    int tid  = threadIdx.x;
    int w    = tid >> 5;
    int lane = tid & 31;
    int g    = lane >> 2;        // 0..7
    int c    = lane & 3;         // 0..3
    int row0 = blockIdx.x * 176;
    long long woff = (long long)layer * DD * DD;

    // ---- load 2 fp16 weight matrices into smem once ----
    {
        const __half* wsrc[2] = { g_Wl16 + woff, g_Wr16 + woff };
        #pragma unroll
        for (int m = 0; m < 2; m++) {
            const uint4* s = reinterpret_cast<const uint4*>(wsrc[m]);  // 16/row
            uint4* d = reinterpret_cast<uint4*>(smem) + m * 2176;      // 17/row
            for (int i = tid; i < 2048; i += 352) {
                int n = i >> 4, c4 = i & 15;
                d[n * 17 + c4] = s[i];
            }
        }
    }
    __syncthreads();

    float acc[16][4];
    #pragma unroll
    for (int t = 0; t < 16; t++)
        #pragma unroll
        for (int j = 0; j < 4; j++) acc[t][j] = 0.f;

    int r1 = row0 + w * 16 + g;
    const u32* pa = reinterpret_cast<const u32*>(g_a16) + (long long)r1 * 64;
    const u32* px = reinterpret_cast<const u32*>(g_x16) + (long long)r1 * 64;

    // double-buffered fp16 A/X fragments (row stride 64 words; +8 rows = +512)
    u32 Aa[2][4], Xx[2][4];
    {
        int kw = c;
        Aa[0][0] = pa[kw]; Aa[0][1] = pa[512 + kw]; Aa[0][2] = pa[kw + 4]; Aa[0][3] = pa[512 + kw + 4];
        Xx[0][0] = px[kw]; Xx[0][1] = px[512 + kw]; Xx[0][2] = px[kw + 4]; Xx[0][3] = px[512 + kw + 4];
    }

    #pragma unroll
    for (int ks = 0; ks < 8; ks++) {
        int cur = ks & 1, nxt = cur ^ 1;
        if (ks < 7) {
            int kw = (ks + 1) * 8 + c;
            Aa[nxt][0] = pa[kw]; Aa[nxt][1] = pa[512 + kw]; Aa[nxt][2] = pa[kw + 4]; Aa[nxt][3] = pa[512 + kw + 4];
            Xx[nxt][0] = px[kw]; Xx[nxt][1] = px[512 + kw]; Xx[nxt][2] = px[kw + 4]; Xx[nxt][3] = px[512 + kw + 4];
        }
        int kwb = ks * 8 + c;
        #pragma unroll
        for (int t = 0; t < 16; t++) {
            int b0 = (t * 8 + g) * 68 + kwb;
            u32 wl[2] = { smem[b0],        smem[b0 + 4] };
            u32 wr[2] = { smem[8704 + b0], smem[8704 + b0 + 4] };
            mma16816h(acc[t], Aa[cur], wl);
            mma16816h(acc[t], Xx[cur], wr);
        }
    }

    // ---- epilogue: bias + relu + residual + LayerNorm ----
    int r2 = r1 + 8;
    float v[16][4];
    #pragma unroll
    for (int t = 0; t < 16; t++) {
        int col = t * 8 + c * 2;
        float2 bb = *reinterpret_cast<const float2*>(bl + col);
        float2 xa = *reinterpret_cast<const float2*>(g_x + (long long)r1 * DD + col);
        float2 xb = *reinterpret_cast<const float2*>(g_x + (long long)r2 * DD + col);
        v[t][0] = fmaxf(acc[t][0] + bb.x, 0.f) + xa.x;
        v[t][1] = fmaxf(acc[t][1] + bb.y, 0.f) + xa.y;
        v[t][2] = fmaxf(acc[t][2] + bb.x, 0.f) + xb.x;
        v[t][3] = fmaxf(acc[t][3] + bb.y, 0.f) + xb.y;
    }
    float s1 = 0.f, q1 = 0.f, s2 = 0.f, q2 = 0.f;
    #pragma unroll
    for (int t = 0; t < 16; t++) {
        s1 += v[t][0] + v[t][1];
        q1 += v[t][0] * v[t][0] + v[t][1] * v[t][1];
        s2 += v[t][2] + v[t][3];
        q2 += v[t][2] * v[t][2] + v[t][3] * v[t][3];
    }
    #pragma unroll
    for (int m = 1; m <= 2; m <<= 1) {
        s1 += __shfl_xor_sync(0xffffffffu, s1, m);
        q1 += __shfl_xor_sync(0xffffffffu, q1, m);
        s2 += __shfl_xor_sync(0xffffffffu, s2, m);
        q2 += __shfl_xor_sync(0xffffffffu, q2, m);
    }
    float mean1 = s1 * (1.0f / DD);
    float var1  = q1 * (1.0f / DD) - mean1 * mean1;
    float rs1   = rsqrtf(var1 + EPS);
    float mean2 = s2 * (1.0f / DD);
    float var2  = q2 * (1.0f / DD) - mean2 * mean2;
    float rs2   = rsqrtf(var2 + EPS);

    bool final = (out_opt != nullptr);
    #pragma unroll
    for (int t = 0; t < 16; t++) {
        int col = t * 8 + c * 2;
        float2 gg = *reinterpret_cast<const float2*>(gamma + col);
        float2 be = *reinterpret_cast<const float2*>(beta + col);
        float2 o1, o2;
        o1.x = (v[t][0] - mean1) * rs1 * gg.x + be.x;
        o1.y = (v[t][1] - mean1) * rs1 * gg.y + be.y;
        o2.x = (v[t][2] - mean2) * rs2 * gg.x + be.x;
        o2.y = (v[t][3] - mean2) * rs2 * gg.y + be.y;
        if (final) {
            if (r1 < NN)
                *reinterpret_cast<float2*>(out_opt + (long long)r1 * DD + col) = o1;
            if (r2 < NN)
                *reinterpret_cast<float2*>(out_opt + (long long)r2 * DD + col) = o2;
        } else {
            *reinterpret_cast<float2*>(g_x + (long long)r1 * DD + col) = o1;
            *reinterpret_cast<float2*>(g_x + (long long)r2 * DD + col) = o2;
            *reinterpret_cast<u32*>(g_x16 + (long long)r1 * DD + col) = pack_h2(o1.x, o1.y);
            *reinterpret_cast<u32*>(g_x16 + (long long)r2 * DD + col) = pack_h2(o2.x, o2.y);
        }
    }
}

extern "C" void kernel_launch(void* const* d_in, const int* in_sizes, int n_in,
                              void* d_out, int out_size)
{
    const float* node_emb  = (const float*)d_in[0];
    const int*   pos       = (const int*)  d_in[1];
    const int*   edge      = (const int*)  d_in[2];
    const float* pos_table = (const float*)d_in[3];
    const float* Wl        = (const float*)d_in[4];
    const float* bl        = (const float*)d_in[5];
    const float* Wr        = (const float*)d_in[6];
    const float* emb_g     = (const float*)d_in[7];
    const float* emb_b     = (const float*)d_in[8];
    const float* hid_g     = (const float*)d_in[9];
    const float* hid_b     = (const float*)d_in[10];
    float* out = (float*)d_out;

    const int SMEM = 2 * 8704 * 4;  // 69632 bytes
    cudaFuncSetAttribute(sage_mma_kernel,
                         cudaFuncAttributeMaxDynamicSharedMemorySize, SMEM);

    // CSR build (once per launch)
    zero_cnt_kernel<<<196, 256>>>();
    hist_off_kernel<<<(EE / 8 + 255) / 256, 256>>>(edge);
    scan_kernel<<<1, 1024>>>();
    fill_kernel<<<(EE / 8 + 255) / 256, 256>>>(edge);

    split_w_kernel<<<192, 256>>>(Wl, Wr);
    embed_ln_kernel<<<NN / 8, 256>>>(node_emb, pos, pos_table, emb_g, emb_b);

    const int gath_grid = NN / 8;             // 6250
    const int gemm_grid = NP / 176;           // 296

    for (int l = 0; l < 3; l++) {
        gather_kernel<<<gath_grid, 256>>>();
        float* outp = (l == 2) ? out : nullptr;
        sage_mma_kernel<<<gemm_grid, 352, SMEM>>>(
            bl + l * DD, hid_g + l * DD, hid_b + l * DD, l, outp);
    }
}